// round 4
// baseline (speedup 1.0000x reference)
#include <cuda_runtime.h>
#include <cuda_bf16.h>

#define NMAX 50000
#define EMAX 800000
#define GRAPHS 64
#define SCAN_B 1024

// ---------------- device scratch (allocation-free rule) ----------------
static __device__ float g_h[NMAX * 128];    // features (post-activation)
static __device__ float g_a[NMAX * 128];    // aggregated features
static __device__ float g_dinv[NMAX];
static __device__ int   g_cnt[NMAX];        // in-degree (no self loop)
static __device__ int   g_rowptr[NMAX + 1];
static __device__ int   g_cursor[NMAX];     // running fill position (abs)
static __device__ int   g_bsum[64];         // per-block scan totals
static __device__ int   g_esrc[EMAX];       // CSR src, grouped by dst
static __device__ float g_psum[GRAPHS * 128];
static __device__ float g_pcnt[GRAPHS];

typedef unsigned long long ull;

// ---------------- f32x2 helpers ----------------
__device__ __forceinline__ ull pack2(float x, float y) {
    ull r; asm("mov.b64 %0, {%1,%2};" : "=l"(r) : "f"(x), "f"(y)); return r;
}
__device__ __forceinline__ void unpack2(ull v, float& x, float& y) {
    asm("mov.b64 {%0,%1}, %2;" : "=f"(x), "=f"(y) : "l"(v));
}
__device__ __forceinline__ ull ffma2(ull a, ull b, ull c) {
    ull d; asm("fma.rn.f32x2 %0, %1, %2, %3;" : "=l"(d) : "l"(a), "l"(b), "l"(c));
    return d;
}

// ---------------- prep ----------------
__global__ void k_zero(int n) {
    int i = blockIdx.x * blockDim.x + threadIdx.x;
    if (i < n) g_cnt[i] = 0;
    if (i < GRAPHS * 128) g_psum[i] = 0.0f;
    if (i < GRAPHS) g_pcnt[i] = 0.0f;
}

__global__ void k_count(const int* __restrict__ dst, int E) {
    int e = blockIdx.x * blockDim.x + threadIdx.x;
    if (e < E) atomicAdd(&g_cnt[dst[e]], 1);
}

// Phase A: per-block exclusive scan of g_cnt -> g_rowptr (local), block totals
// to g_bsum. Also computes dinv (reads g_cnt anyway).
__global__ void k_scanA(int n) {
    __shared__ int swarp[32];
    int t = threadIdx.x;            // 1024
    int i = blockIdx.x * SCAN_B + t;
    int lane = t & 31, wid = t >> 5;
    int v = (i < n) ? g_cnt[i] : 0;
    if (i < n) g_dinv[i] = rsqrtf((float)v + 1.0f);
    int incl = v;
#pragma unroll
    for (int off = 1; off < 32; off <<= 1) {
        int y = __shfl_up_sync(0xffffffffu, incl, off);
        if (lane >= off) incl += y;
    }
    if (lane == 31) swarp[wid] = incl;
    __syncthreads();
    if (wid == 0) {
        int w = swarp[lane];
#pragma unroll
        for (int off = 1; off < 32; off <<= 1) {
            int y = __shfl_up_sync(0xffffffffu, w, off);
            if (lane >= off) w += y;
        }
        swarp[lane] = w;
    }
    __syncthreads();
    int excl = incl - v + ((wid > 0) ? swarp[wid - 1] : 0);
    if (i < n) g_rowptr[i] = excl;
    if (t == SCAN_B - 1) g_bsum[blockIdx.x] = excl + v;
}

// Phase B: single block scans the <=64 block totals in-place (exclusive).
__global__ void k_scanB(int nb) {
    __shared__ int swarp[32];
    int t = threadIdx.x;
    int lane = t & 31, wid = t >> 5;
    int v = (t < nb) ? g_bsum[t] : 0;
    int incl = v;
#pragma unroll
    for (int off = 1; off < 32; off <<= 1) {
        int y = __shfl_up_sync(0xffffffffu, incl, off);
        if (lane >= off) incl += y;
    }
    if (lane == 31) swarp[wid] = incl;
    __syncthreads();
    if (wid == 0) {
        int w = swarp[lane];
#pragma unroll
        for (int off = 1; off < 32; off <<= 1) {
            int y = __shfl_up_sync(0xffffffffu, w, off);
            if (lane >= off) w += y;
        }
        swarp[lane] = w;
    }
    __syncthreads();
    int excl = incl - v + ((wid > 0) ? swarp[wid - 1] : 0);
    if (t < nb) g_bsum[t] = excl;
}

// Phase C: add block offsets; init cursor to absolute rowptr; finalize rowptr[n].
__global__ void k_scanC(int n, int E) {
    int i = blockIdx.x * blockDim.x + threadIdx.x;
    if (i < n) {
        int rp = g_rowptr[i] + g_bsum[i >> 10];
        g_rowptr[i] = rp;
        g_cursor[i] = rp;
    }
    if (i == 0) g_rowptr[n] = E;
}

__global__ void k_fill(const int* __restrict__ src, const int* __restrict__ dst, int E) {
    int e = blockIdx.x * blockDim.x + threadIdx.x;
    if (e < E) {
        int pos = atomicAdd(&g_cursor[dst[e]], 1);
        g_esrc[pos] = src[e];
    }
}

// ---------------- aggregation (pull, CSR) ----------------
// agg_i = dinv_i * ( sum_s dinv_s * h_s  +  dinv_i * h_i )
// C=3 special: thread per node
__global__ void k_agg3(const float* __restrict__ x, int n) {
    int i = blockIdx.x * blockDim.x + threadIdx.x;
    if (i >= n) return;
    int beg = g_rowptr[i], end = g_rowptr[i + 1];
    float di = g_dinv[i];
    float a0 = x[i * 3 + 0] * di, a1 = x[i * 3 + 1] * di, a2 = x[i * 3 + 2] * di;
    for (int j = beg; j < end; j++) {
        int s = g_esrc[j];
        float w = __ldg(&g_dinv[s]);
        a0 += x[s * 3 + 0] * w;
        a1 += x[s * 3 + 1] * w;
        a2 += x[s * 3 + 2] * w;
    }
    g_a[i * 3 + 0] = a0 * di; g_a[i * 3 + 1] = a1 * di; g_a[i * 3 + 2] = a2 * di;
}

// warp per node; VPL floats per lane (C = 32*VPL), vectorized loads
template <int VPL>
__global__ void k_agg(int n) {
    const int C = 32 * VPL;
    int warp = (blockIdx.x * blockDim.x + threadIdx.x) >> 5;
    int lane = threadIdx.x & 31;
    if (warp >= n) return;
    int i = warp;
    int beg = g_rowptr[i], end = g_rowptr[i + 1];
    float di = g_dinv[i];
    float acc[VPL];
    const float* __restrict__ hp = g_h;
#pragma unroll
    for (int v = 0; v < VPL; v++) acc[v] = hp[i * C + lane * VPL + v] * di;

    int j = beg;
    for (; j + 4 <= end; j += 4) {
        int s0 = g_esrc[j], s1 = g_esrc[j + 1], s2 = g_esrc[j + 2], s3 = g_esrc[j + 3];
        float w0 = __ldg(&g_dinv[s0]), w1 = __ldg(&g_dinv[s1]);
        float w2 = __ldg(&g_dinv[s2]), w3 = __ldg(&g_dinv[s3]);
        if (VPL == 4) {
            float4 v0 = *(const float4*)&hp[s0 * C + lane * 4];
            float4 v1 = *(const float4*)&hp[s1 * C + lane * 4];
            float4 v2 = *(const float4*)&hp[s2 * C + lane * 4];
            float4 v3 = *(const float4*)&hp[s3 * C + lane * 4];
            acc[0] += v0.x * w0 + v1.x * w1 + v2.x * w2 + v3.x * w3;
            acc[1] += v0.y * w0 + v1.y * w1 + v2.y * w2 + v3.y * w3;
            acc[2] += v0.z * w0 + v1.z * w1 + v2.z * w2 + v3.z * w3;
            acc[3] += v0.w * w0 + v1.w * w1 + v2.w * w2 + v3.w * w3;
        } else {
            float2 v0 = *(const float2*)&hp[s0 * C + lane * 2];
            float2 v1 = *(const float2*)&hp[s1 * C + lane * 2];
            float2 v2 = *(const float2*)&hp[s2 * C + lane * 2];
            float2 v3 = *(const float2*)&hp[s3 * C + lane * 2];
            acc[0] += v0.x * w0 + v1.x * w1 + v2.x * w2 + v3.x * w3;
            acc[1] += v0.y * w0 + v1.y * w1 + v2.y * w2 + v3.y * w3;
        }
    }
    for (; j < end; j++) {
        int s = g_esrc[j];
        float w = __ldg(&g_dinv[s]);
        if (VPL == 4) {
            float4 v = *(const float4*)&hp[s * C + lane * 4];
            acc[0] += v.x * w; acc[1] += v.y * w; acc[2] += v.z * w; acc[3] += v.w * w;
        } else {
            float2 v = *(const float2*)&hp[s * C + lane * 2];
            acc[0] += v.x * w; acc[1] += v.y * w;
        }
    }
    if (VPL == 4) {
        float4 o; o.x = acc[0] * di; o.y = acc[1] * di; o.z = acc[2] * di; o.w = acc[3] * di;
        *(float4*)&g_a[i * C + lane * 4] = o;
    } else {
        float2 o; o.x = acc[0] * di; o.y = acc[1] * di;
        *(float2*)&g_a[i * C + lane * 2] = o;
    }
}

// ---------------- GEMM + bias + relu:  g_h = relu(g_a @ W + b) ----------------
// K=3 special (layer 1): one thread per output element
__global__ void k_gemm3(const float* __restrict__ W, const float* __restrict__ b, int n) {
    int idx = blockIdx.x * blockDim.x + threadIdx.x;
    if (idx >= n * 64) return;
    int row = idx >> 6, c = idx & 63;
    float a0 = g_a[row * 3 + 0], a1 = g_a[row * 3 + 1], a2 = g_a[row * 3 + 2];
    float acc = b[c] + a0 * W[c] + a1 * W[64 + c] + a2 * W[128 + c];
    g_h[row * 64 + c] = fmaxf(acc, 0.0f);
}

// K in {64,128}, C=128. Block: dim3(64,8) = 512 thr. 64 rows/block,
// each thread: 8 rows x 2 channels, f32x2 accumulators.
// W fetched from L2 once per block (50 MB total for K=128).
template <int K>
__global__ void __launch_bounds__(512) k_gemm(const float* __restrict__ W,
                                              const float* __restrict__ b, int n) {
    const int C = 128, ROWS = 64, RPT = 8;
    __shared__ float sh[ROWS][K];
    int tc = threadIdx.x;            // 0..63 -> channels 2tc, 2tc+1
    int ty = threadIdx.y;            // 0..7
    int tid = ty * 64 + tc;
    int row0 = blockIdx.x * ROWS;

    const int NV = ROWS * K / 4;
    for (int v = tid; v < NV; v += 512) {
        int o = v * 4;
        int r = o / K, k = o - r * K;
        int row = row0 + r;
        float4 val = (row < n) ? *(const float4*)&g_a[row * K + k]
                               : make_float4(0.f, 0.f, 0.f, 0.f);
        *(float4*)&sh[r][k] = val;
    }
    __syncthreads();

    const ull* __restrict__ Wll = (const ull*)W;
    ull acc[RPT];
    {
        float2 bb = *(const float2*)&b[2 * tc];
        ull binit = pack2(bb.x, bb.y);
#pragma unroll
        for (int r = 0; r < RPT; r++) acc[r] = binit;
    }
    int rbase = ty * RPT;
#pragma unroll 4
    for (int k = 0; k < K; k += 2) {
        ull w0 = Wll[k * (C / 2) + tc];
        ull w1 = Wll[(k + 1) * (C / 2) + tc];
#pragma unroll
        for (int r = 0; r < RPT; r++) {
            float2 s2 = *(const float2*)&sh[rbase + r][k];
            acc[r] = ffma2(pack2(s2.x, s2.x), w0, acc[r]);
            acc[r] = ffma2(pack2(s2.y, s2.y), w1, acc[r]);
        }
    }
#pragma unroll
    for (int r = 0; r < RPT; r++) {
        int row = row0 + rbase + r;
        if (row < n) {
            float x, y; unpack2(acc[r], x, y);
            float2 o; o.x = fmaxf(x, 0.0f); o.y = fmaxf(y, 0.0f);
            *(float2*)&g_h[row * C + 2 * tc] = o;
        }
    }
}

// ---------------- mean pool over sorted batch ----------------
__global__ void k_pool(const int* __restrict__ batch, int n) {
    const int NPB = 256;
    int c = threadIdx.x;  // 128 threads
    int i0 = blockIdx.x * NPB;
    int cur = -1, cnt = 0;
    float acc = 0.0f;
    for (int j = 0; j < NPB; j++) {
        int i = i0 + j;
        if (i >= n) break;
        int g = __ldg(&batch[i]);
        if (g != cur) {
            if (cur >= 0) {
                atomicAdd(&g_psum[cur * 128 + c], acc);
                if (c == 0) atomicAdd(&g_pcnt[cur], (float)cnt);
            }
            cur = g; acc = 0.0f; cnt = 0;
        }
        acc += g_h[i * 128 + c];
        cnt++;
    }
    if (cur >= 0) {
        atomicAdd(&g_psum[cur * 128 + c], acc);
        if (c == 0) atomicAdd(&g_pcnt[cur], (float)cnt);
    }
}

// ---------------- MLP head ----------------
__global__ void k_fc(const float* __restrict__ Wf1, const float* __restrict__ bf1,
                     const float* __restrict__ Wf2, const float* __restrict__ bf2,
                     float* __restrict__ out) {
    int g = blockIdx.x;
    int t = threadIdx.x;  // 128
    __shared__ float p[128];
    __shared__ float f1[64];
    float inv = 1.0f / fmaxf(g_pcnt[g], 1.0f);
    p[t] = g_psum[g * 128 + t] * inv;
    __syncthreads();
    if (t < 64) {
        float acc = bf1[t];
#pragma unroll
        for (int k = 0; k < 128; k++) acc += p[k] * Wf1[k * 64 + t];
        f1[t] = fmaxf(acc, 0.0f);
    }
    __syncthreads();
    if (t < 10) {
        float acc = bf2[t];
#pragma unroll
        for (int k = 0; k < 64; k++) acc += f1[k] * Wf2[k * 10 + t];
        out[g * 10 + t] = acc;
    }
}

extern "C" void kernel_launch(void* const* d_in, const int* in_sizes, int n_in,
                              void* d_out, int out_size) {
    const float* x   = (const float*)d_in[0];
    const int* ei    = (const int*)d_in[1];
    const int* batch = (const int*)d_in[2];
    const float* W1  = (const float*)d_in[3];
    const float* b1  = (const float*)d_in[4];
    const float* W2  = (const float*)d_in[5];
    const float* b2  = (const float*)d_in[6];
    const float* W3  = (const float*)d_in[7];
    const float* b3  = (const float*)d_in[8];
    const float* Wf1 = (const float*)d_in[9];
    const float* bf1 = (const float*)d_in[10];
    const float* Wf2 = (const float*)d_in[11];
    const float* bf2 = (const float*)d_in[12];
    float* out = (float*)d_out;

    int N = in_sizes[0] / 3;
    int E = in_sizes[1] / 2;
    const int* src = ei;
    const int* dst = ei + E;
    int NB = (N + SCAN_B - 1) / SCAN_B;

    // CSR (by dst) once per launch, reused by all 3 layers
    k_zero<<<(N + 255) / 256, 256>>>(N);
    k_count<<<(E + 255) / 256, 256>>>(dst, E);
    k_scanA<<<NB, SCAN_B>>>(N);
    k_scanB<<<1, SCAN_B>>>(NB);
    k_scanC<<<(N + 255) / 256, 256>>>(N, E);
    k_fill<<<(E + 255) / 256, 256>>>(src, dst, E);

    // Layer 1: aggregate at C=3, then 3->64 transform
    k_agg3<<<(N + 127) / 128, 128>>>(x, N);
    k_gemm3<<<(N * 64 + 255) / 256, 256>>>(W1, b1, N);

    // Layer 2: aggregate at C=64, then 64->128
    k_agg<2><<<(N + 7) / 8, 256>>>(N);
    k_gemm<64><<<(N + 63) / 64, dim3(64, 8)>>>(W2, b2, N);

    // Layer 3: aggregate at C=128, then 128->128
    k_agg<4><<<(N + 7) / 8, 256>>>(N);
    k_gemm<128><<<(N + 63) / 64, dim3(64, 8)>>>(W3, b3, N);

    // Pool + head
    k_pool<<<(N + 255) / 256, 128>>>(batch, N);
    k_fc<<<GRAPHS, 128>>>(Wf1, bf1, Wf2, bf2, out);
}

// round 5
// speedup vs baseline: 1.0889x; 1.0889x over previous
#include <cuda_runtime.h>
#include <cuda_bf16.h>
#include <cuda_fp16.h>

#define NMAX 50000
#define EMAX 800000
#define GRAPHS 64
#define SCAN_B 1024

// ---------------- device scratch (allocation-free rule) ----------------
static __device__ __half g_hh[NMAX * 128]; // features (post-activation), fp16
static __device__ float g_a[NMAX * 128];    // aggregated features, fp32
static __device__ float g_dinv[NMAX];
static __device__ int   g_cnt[NMAX];        // in-degree (no self loop)
static __device__ int   g_rowptr[NMAX + 1];
static __device__ int   g_cursor[NMAX];
static __device__ int   g_bsum[64];         // per-block scan totals
static __device__ int   g_esrc[EMAX];       // CSR src, grouped by dst
static __device__ float g_enorm[EMAX];      // per-edge norm, same order
static __device__ float g_psum[GRAPHS * 128];
static __device__ float g_pcnt[GRAPHS];

typedef unsigned long long ull;

// ---------------- f32x2 helpers ----------------
__device__ __forceinline__ ull pack2(float x, float y) {
    ull r; asm("mov.b64 %0, {%1,%2};" : "=l"(r) : "f"(x), "f"(y)); return r;
}
__device__ __forceinline__ void unpack2(ull v, float& x, float& y) {
    asm("mov.b64 {%0,%1}, %2;" : "=f"(x), "=f"(y) : "l"(v));
}
__device__ __forceinline__ ull ffma2(ull a, ull b, ull c) {
    ull d; asm("fma.rn.f32x2 %0, %1, %2, %3;" : "=l"(d) : "l"(a), "l"(b), "l"(c));
    return d;
}

// ---------------- prep ----------------
__global__ void k_zero(int n) {
    int i = blockIdx.x * blockDim.x + threadIdx.x;
    if (i < n) g_cnt[i] = 0;
    if (i < GRAPHS * 128) g_psum[i] = 0.0f;
    if (i < GRAPHS) g_pcnt[i] = 0.0f;
}

__global__ void k_count(const int* __restrict__ dst, int E) {
    int e = blockIdx.x * blockDim.x + threadIdx.x;
    if (e < E) atomicAdd(&g_cnt[dst[e]], 1);
}

// Phase A: per-block exclusive scan of g_cnt -> g_rowptr (local), block totals
// to g_bsum. Also computes dinv (reads g_cnt anyway).
__global__ void k_scanA(int n) {
    __shared__ int swarp[32];
    int t = threadIdx.x;            // 1024
    int i = blockIdx.x * SCAN_B + t;
    int lane = t & 31, wid = t >> 5;
    int v = (i < n) ? g_cnt[i] : 0;
    if (i < n) g_dinv[i] = rsqrtf((float)v + 1.0f);
    int incl = v;
#pragma unroll
    for (int off = 1; off < 32; off <<= 1) {
        int y = __shfl_up_sync(0xffffffffu, incl, off);
        if (lane >= off) incl += y;
    }
    if (lane == 31) swarp[wid] = incl;
    __syncthreads();
    if (wid == 0) {
        int w = swarp[lane];
#pragma unroll
        for (int off = 1; off < 32; off <<= 1) {
            int y = __shfl_up_sync(0xffffffffu, w, off);
            if (lane >= off) w += y;
        }
        swarp[lane] = w;
    }
    __syncthreads();
    int excl = incl - v + ((wid > 0) ? swarp[wid - 1] : 0);
    if (i < n) g_rowptr[i] = excl;
    if (t == SCAN_B - 1) g_bsum[blockIdx.x] = excl + v;
}

// Phase B: single block scans the <=64 block totals in-place (exclusive).
__global__ void k_scanB(int nb) {
    __shared__ int swarp[32];
    int t = threadIdx.x;
    int lane = t & 31, wid = t >> 5;
    int v = (t < nb) ? g_bsum[t] : 0;
    int incl = v;
#pragma unroll
    for (int off = 1; off < 32; off <<= 1) {
        int y = __shfl_up_sync(0xffffffffu, incl, off);
        if (lane >= off) incl += y;
    }
    if (lane == 31) swarp[wid] = incl;
    __syncthreads();
    if (wid == 0) {
        int w = swarp[lane];
#pragma unroll
        for (int off = 1; off < 32; off <<= 1) {
            int y = __shfl_up_sync(0xffffffffu, w, off);
            if (lane >= off) w += y;
        }
        swarp[lane] = w;
    }
    __syncthreads();
    int excl = incl - v + ((wid > 0) ? swarp[wid - 1] : 0);
    if (t < nb) g_bsum[t] = excl;
}

// Phase C: add block offsets; zero cursor; finalize rowptr[n].
__global__ void k_scanC(int n, int E) {
    int i = blockIdx.x * blockDim.x + threadIdx.x;
    if (i < n) {
        g_rowptr[i] += g_bsum[i >> 10];
        g_cursor[i] = 0;
    }
    if (i == 0) g_rowptr[n] = E;
}

__global__ void k_fill(const int* __restrict__ src, const int* __restrict__ dst, int E) {
    int e = blockIdx.x * blockDim.x + threadIdx.x;
    if (e < E) {
        int s = src[e], d = dst[e];
        int pos = g_rowptr[d] + atomicAdd(&g_cursor[d], 1);
        g_esrc[pos] = s;
        g_enorm[pos] = g_dinv[s] * g_dinv[d];
    }
}

// ---------------- aggregation (pull, CSR) ----------------
// C=3 special: thread per node (reads fp32 x directly)
__global__ void k_agg3(const float* __restrict__ x, int n) {
    int i = blockIdx.x * blockDim.x + threadIdx.x;
    if (i >= n) return;
    int beg = g_rowptr[i], end = g_rowptr[i + 1];
    float di = g_dinv[i];
    float w0 = di * di;
    float a0 = x[i * 3 + 0] * w0, a1 = x[i * 3 + 1] * w0, a2 = x[i * 3 + 2] * w0;
    for (int j = beg; j < end; j++) {
        int s = g_esrc[j];
        float w = g_enorm[j];
        a0 += x[s * 3 + 0] * w;
        a1 += x[s * 3 + 1] * w;
        a2 += x[s * 3 + 2] * w;
    }
    g_a[i * 3 + 0] = a0; g_a[i * 3 + 1] = a1; g_a[i * 3 + 2] = a2;
}

// warp per node; VPL fp16 values per lane (C = 32*VPL), fp32 accumulation.
template <int VPL>
__global__ void k_agg(int n) {
    const int C = 32 * VPL;
    int warp = (blockIdx.x * blockDim.x + threadIdx.x) >> 5;
    int lane = threadIdx.x & 31;
    if (warp >= n) return;
    int i = warp;
    int beg = g_rowptr[i], end = g_rowptr[i + 1];
    float di = g_dinv[i];
    float sw = di * di;
    float acc[VPL];
    const __half* __restrict__ hp = g_hh;

    // self term
    if (VPL == 4) {
        uint2 u = *(const uint2*)(hp + i * C + lane * 4);
        float2 f0 = __half22float2(*reinterpret_cast<__half2*>(&u.x));
        float2 f1 = __half22float2(*reinterpret_cast<__half2*>(&u.y));
        acc[0] = f0.x * sw; acc[1] = f0.y * sw; acc[2] = f1.x * sw; acc[3] = f1.y * sw;
    } else {
        unsigned u = *(const unsigned*)(hp + i * C + lane * 2);
        float2 f0 = __half22float2(*reinterpret_cast<__half2*>(&u));
        acc[0] = f0.x * sw; acc[1] = f0.y * sw;
    }

    int j = beg;
    for (; j + 4 <= end; j += 4) {
        int s0 = g_esrc[j], s1 = g_esrc[j + 1], s2 = g_esrc[j + 2], s3 = g_esrc[j + 3];
        float w0 = g_enorm[j], w1 = g_enorm[j + 1], w2 = g_enorm[j + 2], w3 = g_enorm[j + 3];
        if (VPL == 4) {
            uint2 u0 = *(const uint2*)(hp + s0 * C + lane * 4);
            uint2 u1 = *(const uint2*)(hp + s1 * C + lane * 4);
            uint2 u2 = *(const uint2*)(hp + s2 * C + lane * 4);
            uint2 u3 = *(const uint2*)(hp + s3 * C + lane * 4);
            float2 a0 = __half22float2(*reinterpret_cast<__half2*>(&u0.x));
            float2 b0 = __half22float2(*reinterpret_cast<__half2*>(&u0.y));
            float2 a1 = __half22float2(*reinterpret_cast<__half2*>(&u1.x));
            float2 b1 = __half22float2(*reinterpret_cast<__half2*>(&u1.y));
            float2 a2 = __half22float2(*reinterpret_cast<__half2*>(&u2.x));
            float2 b2 = __half22float2(*reinterpret_cast<__half2*>(&u2.y));
            float2 a3 = __half22float2(*reinterpret_cast<__half2*>(&u3.x));
            float2 b3 = __half22float2(*reinterpret_cast<__half2*>(&u3.y));
            acc[0] += a0.x * w0 + a1.x * w1 + a2.x * w2 + a3.x * w3;
            acc[1] += a0.y * w0 + a1.y * w1 + a2.y * w2 + a3.y * w3;
            acc[2] += b0.x * w0 + b1.x * w1 + b2.x * w2 + b3.x * w3;
            acc[3] += b0.y * w0 + b1.y * w1 + b2.y * w2 + b3.y * w3;
        } else {
            unsigned u0 = *(const unsigned*)(hp + s0 * C + lane * 2);
            unsigned u1 = *(const unsigned*)(hp + s1 * C + lane * 2);
            unsigned u2 = *(const unsigned*)(hp + s2 * C + lane * 2);
            unsigned u3 = *(const unsigned*)(hp + s3 * C + lane * 2);
            float2 a0 = __half22float2(*reinterpret_cast<__half2*>(&u0));
            float2 a1 = __half22float2(*reinterpret_cast<__half2*>(&u1));
            float2 a2 = __half22float2(*reinterpret_cast<__half2*>(&u2));
            float2 a3 = __half22float2(*reinterpret_cast<__half2*>(&u3));
            acc[0] += a0.x * w0 + a1.x * w1 + a2.x * w2 + a3.x * w3;
            acc[1] += a0.y * w0 + a1.y * w1 + a2.y * w2 + a3.y * w3;
        }
    }
    for (; j < end; j++) {
        int s = g_esrc[j];
        float w = g_enorm[j];
        if (VPL == 4) {
            uint2 u = *(const uint2*)(hp + s * C + lane * 4);
            float2 f0 = __half22float2(*reinterpret_cast<__half2*>(&u.x));
            float2 f1 = __half22float2(*reinterpret_cast<__half2*>(&u.y));
            acc[0] += f0.x * w; acc[1] += f0.y * w; acc[2] += f1.x * w; acc[3] += f1.y * w;
        } else {
            unsigned u = *(const unsigned*)(hp + s * C + lane * 2);
            float2 f0 = __half22float2(*reinterpret_cast<__half2*>(&u));
            acc[0] += f0.x * w; acc[1] += f0.y * w;
        }
    }
    if (VPL == 4) {
        float4 o; o.x = acc[0]; o.y = acc[1]; o.z = acc[2]; o.w = acc[3];
        *(float4*)&g_a[i * C + lane * 4] = o;
    } else {
        float2 o; o.x = acc[0]; o.y = acc[1];
        *(float2*)&g_a[i * C + lane * 2] = o;
    }
}

// ---------------- GEMM + bias + relu:  g_hh = fp16(relu(g_a @ W + b)) --------
// K=3 special (layer 1): one thread per output element
__global__ void k_gemm3(const float* __restrict__ W, const float* __restrict__ b, int n) {
    int idx = blockIdx.x * blockDim.x + threadIdx.x;
    if (idx >= n * 64) return;
    int row = idx >> 6, c = idx & 63;
    float a0 = g_a[row * 3 + 0], a1 = g_a[row * 3 + 1], a2 = g_a[row * 3 + 2];
    float acc = b[c] + a0 * W[c] + a1 * W[64 + c] + a2 * W[128 + c];
    g_hh[row * 64 + c] = __float2half(fmaxf(acc, 0.0f));
}

// K in {64,128}, C=128. Block: dim3(64,2) = 128 thr. 16 rows/block,
// each thread: 8 rows x 2 channels, f32x2 accumulators, fp16 store.
template <int K>
__global__ void k_gemm(const float* __restrict__ W, const float* __restrict__ b, int n) {
    const int C = 128, ROWS = 16, RPT = 8;
    __shared__ float sh[ROWS][K];
    int tc = threadIdx.x;            // 0..63 -> channels 2tc, 2tc+1
    int ty = threadIdx.y;            // 0..1
    int tid = ty * 64 + tc;
    int row0 = blockIdx.x * ROWS;

    const int NV = ROWS * K / 4;
    for (int v = tid; v < NV; v += 128) {
        int o = v * 4;
        int r = o / K, k = o - r * K;
        int row = row0 + r;
        float4 val = (row < n) ? *(const float4*)&g_a[row * K + k]
                               : make_float4(0.f, 0.f, 0.f, 0.f);
        *(float4*)&sh[r][k] = val;
    }
    __syncthreads();

    const ull* __restrict__ Wll = (const ull*)W;
    ull acc[RPT];
    {
        float2 bb = *(const float2*)&b[2 * tc];
        ull binit = pack2(bb.x, bb.y);
#pragma unroll
        for (int r = 0; r < RPT; r++) acc[r] = binit;
    }
    int rbase = ty * RPT;
#pragma unroll 4
    for (int k = 0; k < K; k += 2) {
        ull w0 = Wll[k * (C / 2) + tc];
        ull w1 = Wll[(k + 1) * (C / 2) + tc];
#pragma unroll
        for (int r = 0; r < RPT; r++) {
            float2 s2 = *(const float2*)&sh[rbase + r][k];
            acc[r] = ffma2(pack2(s2.x, s2.x), w0, acc[r]);
            acc[r] = ffma2(pack2(s2.y, s2.y), w1, acc[r]);
        }
    }
#pragma unroll
    for (int r = 0; r < RPT; r++) {
        int row = row0 + rbase + r;
        if (row < n) {
            float x, y; unpack2(acc[r], x, y);
            __half2 o = __floats2half2_rn(fmaxf(x, 0.0f), fmaxf(y, 0.0f));
            *(__half2*)&g_hh[row * C + 2 * tc] = o;
        }
    }
}

// ---------------- mean pool over sorted batch (reads fp16 h) ----------------
__global__ void k_pool(const int* __restrict__ batch, int n) {
    const int NPB = 256;
    int c = threadIdx.x;  // 128 threads
    int i0 = blockIdx.x * NPB;
    int cur = -1, cnt = 0;
    float acc = 0.0f;
    for (int j = 0; j < NPB; j++) {
        int i = i0 + j;
        if (i >= n) break;
        int g = __ldg(&batch[i]);
        if (g != cur) {
            if (cur >= 0) {
                atomicAdd(&g_psum[cur * 128 + c], acc);
                if (c == 0) atomicAdd(&g_pcnt[cur], (float)cnt);
            }
            cur = g; acc = 0.0f; cnt = 0;
        }
        acc += __half2float(g_hh[i * 128 + c]);
        cnt++;
    }
    if (cur >= 0) {
        atomicAdd(&g_psum[cur * 128 + c], acc);
        if (c == 0) atomicAdd(&g_pcnt[cur], (float)cnt);
    }
}

// ---------------- MLP head ----------------
__global__ void k_fc(const float* __restrict__ Wf1, const float* __restrict__ bf1,
                     const float* __restrict__ Wf2, const float* __restrict__ bf2,
                     float* __restrict__ out) {
    int g = blockIdx.x;
    int t = threadIdx.x;  // 128
    __shared__ float p[128];
    __shared__ float f1[64];
    float inv = 1.0f / fmaxf(g_pcnt[g], 1.0f);
    p[t] = g_psum[g * 128 + t] * inv;
    __syncthreads();
    if (t < 64) {
        float acc = bf1[t];
#pragma unroll
        for (int k = 0; k < 128; k++) acc += p[k] * Wf1[k * 64 + t];
        f1[t] = fmaxf(acc, 0.0f);
    }
    __syncthreads();
    if (t < 10) {
        float acc = bf2[t];
#pragma unroll
        for (int k = 0; k < 64; k++) acc += f1[k] * Wf2[k * 10 + t];
        out[g * 10 + t] = acc;
    }
}

extern "C" void kernel_launch(void* const* d_in, const int* in_sizes, int n_in,
                              void* d_out, int out_size) {
    const float* x   = (const float*)d_in[0];
    const int* ei    = (const int*)d_in[1];
    const int* batch = (const int*)d_in[2];
    const float* W1  = (const float*)d_in[3];
    const float* b1  = (const float*)d_in[4];
    const float* W2  = (const float*)d_in[5];
    const float* b2  = (const float*)d_in[6];
    const float* W3  = (const float*)d_in[7];
    const float* b3  = (const float*)d_in[8];
    const float* Wf1 = (const float*)d_in[9];
    const float* bf1 = (const float*)d_in[10];
    const float* Wf2 = (const float*)d_in[11];
    const float* bf2 = (const float*)d_in[12];
    float* out = (float*)d_out;

    int N = in_sizes[0] / 3;
    int E = in_sizes[1] / 2;
    const int* src = ei;
    const int* dst = ei + E;
    int NB = (N + SCAN_B - 1) / SCAN_B;

    // CSR + norms (once per launch, reused by all 3 layers)
    k_zero<<<(N + 255) / 256, 256>>>(N);
    k_count<<<(E + 255) / 256, 256>>>(dst, E);
    k_scanA<<<NB, SCAN_B>>>(N);
    k_scanB<<<1, SCAN_B>>>(NB);
    k_scanC<<<(N + 255) / 256, 256>>>(N, E);
    k_fill<<<(E + 255) / 256, 256>>>(src, dst, E);

    // Layer 1: aggregate at C=3, then 3->64 transform
    k_agg3<<<(N + 127) / 128, 128>>>(x, N);
    k_gemm3<<<(N * 64 + 255) / 256, 256>>>(W1, b1, N);

    // Layer 2: aggregate at C=64, then 64->128
    k_agg<2><<<(N + 7) / 8, 256>>>(N);
    k_gemm<64><<<(N + 15) / 16, dim3(64, 2)>>>(W2, b2, N);

    // Layer 3: aggregate at C=128, then 128->128
    k_agg<4><<<(N + 7) / 8, 256>>>(N);
    k_gemm<128><<<(N + 15) / 16, dim3(64, 2)>>>(W3, b3, N);

    // Pool + head
    k_pool<<<(N + 255) / 256, 128>>>(batch, N);
    k_fc<<<GRAPHS, 128>>>(Wf1, bf1, Wf2, bf2, out);
}

// round 6
// speedup vs baseline: 1.1540x; 1.0598x over previous
#include <cuda_runtime.h>
#include <cuda_bf16.h>
#include <cuda_fp16.h>

#define NMAX 50000
#define EMAX 800000
#define GRAPHS 64
#define SCAN_B 1024

// ---------------- device scratch (allocation-free rule) ----------------
static __device__ __half g_h0[NMAX * 64];   // layer-1 output, fp16
static __device__ __half g_h1[NMAX * 128];  // layer-2 output, fp16
static __device__ float g_dinv[NMAX];
static __device__ int   g_cnt[NMAX];
static __device__ int   g_rowptr[NMAX + 1];
static __device__ int   g_cursor[NMAX];
static __device__ int   g_bsum[64];
static __device__ int   g_esrc[EMAX];       // CSR src, grouped by dst
static __device__ float g_enorm[EMAX];      // per-edge norm, same order
static __device__ float g_psum[GRAPHS * 128];
static __device__ float g_pcnt[GRAPHS];

typedef unsigned long long ull;

// ---------------- f32x2 helpers ----------------
__device__ __forceinline__ ull pack2(float x, float y) {
    ull r; asm("mov.b64 %0, {%1,%2};" : "=l"(r) : "f"(x), "f"(y)); return r;
}
__device__ __forceinline__ void unpack2(ull v, float& x, float& y) {
    asm("mov.b64 {%0,%1}, %2;" : "=f"(x), "=f"(y) : "l"(v));
}
__device__ __forceinline__ ull ffma2(ull a, ull b, ull c) {
    ull d; asm("fma.rn.f32x2 %0, %1, %2, %3;" : "=l"(d) : "l"(a), "l"(b), "l"(c));
    return d;
}

// ---------------- prep ----------------
__global__ void k_zero(int n) {
    int i = blockIdx.x * blockDim.x + threadIdx.x;
    if (i < n) g_cnt[i] = 0;
    if (i < GRAPHS * 128) g_psum[i] = 0.0f;
    if (i < GRAPHS) g_pcnt[i] = 0.0f;
}

// degree histogram + graph-size histogram (batch) in one pass
__global__ void k_count(const int* __restrict__ dst, const int* __restrict__ batch,
                        int E, int n) {
    int e = blockIdx.x * blockDim.x + threadIdx.x;
    if (e < E) atomicAdd(&g_cnt[dst[e]], 1);
    if (e < n) atomicAdd(&g_pcnt[batch[e]], 1.0f);
}

// Phase A: per-block exclusive scan of g_cnt -> g_rowptr (local) + block totals.
__global__ void k_scanA(int n) {
    __shared__ int swarp[32];
    int t = threadIdx.x;            // 1024
    int i = blockIdx.x * SCAN_B + t;
    int lane = t & 31, wid = t >> 5;
    int v = (i < n) ? g_cnt[i] : 0;
    if (i < n) g_dinv[i] = rsqrtf((float)v + 1.0f);
    int incl = v;
#pragma unroll
    for (int off = 1; off < 32; off <<= 1) {
        int y = __shfl_up_sync(0xffffffffu, incl, off);
        if (lane >= off) incl += y;
    }
    if (lane == 31) swarp[wid] = incl;
    __syncthreads();
    if (wid == 0) {
        int w = swarp[lane];
#pragma unroll
        for (int off = 1; off < 32; off <<= 1) {
            int y = __shfl_up_sync(0xffffffffu, w, off);
            if (lane >= off) w += y;
        }
        swarp[lane] = w;
    }
    __syncthreads();
    int excl = incl - v + ((wid > 0) ? swarp[wid - 1] : 0);
    if (i < n) g_rowptr[i] = excl;
    if (t == SCAN_B - 1) g_bsum[blockIdx.x] = excl + v;
}

// Phase C (absorbs old scanB): each block prefixes the <=49 block totals
// itself, then adds offsets, zeroes cursor, finalizes rowptr[n].
__global__ void k_scanC(int n, int E, int nb) {
    __shared__ int pref[64];
    if (threadIdx.x == 0) {
        int s = 0;
        for (int j = 0; j < nb; j++) { pref[j] = s; s += g_bsum[j]; }
    }
    __syncthreads();
    int i = blockIdx.x * blockDim.x + threadIdx.x;
    if (i < n) {
        g_rowptr[i] += pref[i >> 10];
        g_cursor[i] = 0;
    }
    if (i == 0) g_rowptr[n] = E;
}

__global__ void k_fill(const int* __restrict__ src, const int* __restrict__ dst, int E) {
    int e = blockIdx.x * blockDim.x + threadIdx.x;
    if (e < E) {
        int s = src[e], d = dst[e];
        int pos = g_rowptr[d] + atomicAdd(&g_cursor[d], 1);
        g_esrc[pos] = s;
        g_enorm[pos] = g_dinv[s] * g_dinv[d];
    }
}

// ---------------- Layer 1 fused: agg(C=3) + 3->64 GEMM + relu -> g_h0 -------
// Block: 256 thr, 64 nodes. Phase A: warp per node, edge-parallel lanes,
// shfl-reduce. Phase B: 4x64 threads, thread = (16 rows x 1 col).
__global__ void __launch_bounds__(256) k_layer1(const float* __restrict__ x,
                                                const float* __restrict__ W,
                                                const float* __restrict__ b, int n) {
    const int NPB = 64;
    __shared__ float sa[NPB][3];
    __shared__ float sW[192];
    __shared__ float sb[64];
    int tid = threadIdx.x, wid = tid >> 5, lane = tid & 31;
    int node0 = blockIdx.x * NPB;
    if (tid < 192) sW[tid] = W[tid];
    if (tid < 64) sb[tid] = b[tid];

    for (int k = 0; k < NPB; k += 8) {
        int lr = k + wid;
        int i = node0 + lr;
        if (i < n) {
            int beg = g_rowptr[i], end = g_rowptr[i + 1];
            float a0 = 0.f, a1 = 0.f, a2 = 0.f;
            for (int j = beg + lane; j < end; j += 32) {
                int s = g_esrc[j];
                float w = g_enorm[j];
                a0 += x[s * 3 + 0] * w;
                a1 += x[s * 3 + 1] * w;
                a2 += x[s * 3 + 2] * w;
            }
#pragma unroll
            for (int off = 16; off > 0; off >>= 1) {
                a0 += __shfl_down_sync(0xffffffffu, a0, off);
                a1 += __shfl_down_sync(0xffffffffu, a1, off);
                a2 += __shfl_down_sync(0xffffffffu, a2, off);
            }
            if (lane == 0) {
                float di = g_dinv[i], sw = di * di;
                sa[lr][0] = a0 + x[i * 3 + 0] * sw;
                sa[lr][1] = a1 + x[i * 3 + 1] * sw;
                sa[lr][2] = a2 + x[i * 3 + 2] * sw;
            }
        }
    }
    __syncthreads();

    int tc = tid & 63, ty = tid >> 6;  // ty 0..3 -> 16 rows each
    float w0 = sW[tc], w1 = sW[64 + tc], w2 = sW[128 + tc], bb = sb[tc];
#pragma unroll 4
    for (int r = 0; r < 16; r++) {
        int lr = ty * 16 + r;
        int row = node0 + lr;
        if (row >= n) break;
        float v = bb + sa[lr][0] * w0 + sa[lr][1] * w1 + sa[lr][2] * w2;
        g_h0[row * 64 + tc] = __float2half(fmaxf(v, 0.0f));
    }
}

// ---------------- Fused layer: agg(K) + KxC GEMM (+relu) -------------------
// K in {64,128}, C=128. Block: 256 thr, 16 nodes.
// Phase A: warp aggregates 2 nodes (VPL=K/32 fp16/lane) into smem (fp32).
// Phase B: tc=0..63 (2 cols), ty=0..3 (4 rows each), f32x2 accum.
// POOL: relu + run-detected atomic mean-pool accumulation (layer 3).
template <int K, int VPL, bool POOL>
__global__ void __launch_bounds__(256) k_layer(const float* __restrict__ W,
                                               const float* __restrict__ b,
                                               const int* __restrict__ batch, int n) {
    const int C = 128, ROWS = 16;
    __shared__ float sh[ROWS][K];
    int tid = threadIdx.x, wid = tid >> 5, lane = tid & 31;
    int row0 = blockIdx.x * ROWS;
    const __half* __restrict__ hp = (K == 64) ? g_h0 : g_h1;

#pragma unroll
    for (int rr = 0; rr < 2; rr++) {
        int lr = wid * 2 + rr;
        int i = row0 + lr;
        if (i < n) {
            int beg = g_rowptr[i], end = g_rowptr[i + 1];
            float di = g_dinv[i], sw = di * di;
            float acc[VPL];
            // self term
            if (VPL == 4) {
                uint2 u = *(const uint2*)(hp + (size_t)i * K + lane * 4);
                float2 f0 = __half22float2(*reinterpret_cast<__half2*>(&u.x));
                float2 f1 = __half22float2(*reinterpret_cast<__half2*>(&u.y));
                acc[0] = f0.x * sw; acc[1] = f0.y * sw; acc[2] = f1.x * sw; acc[3] = f1.y * sw;
            } else {
                unsigned u = *(const unsigned*)(hp + (size_t)i * K + lane * 2);
                float2 f0 = __half22float2(*reinterpret_cast<__half2*>(&u));
                acc[0] = f0.x * sw; acc[1] = f0.y * sw;
            }
            int j = beg;
            for (; j + 4 <= end; j += 4) {
                int s0 = g_esrc[j], s1 = g_esrc[j + 1], s2 = g_esrc[j + 2], s3 = g_esrc[j + 3];
                float w0 = g_enorm[j], w1 = g_enorm[j + 1];
                float w2 = g_enorm[j + 2], w3 = g_enorm[j + 3];
                if (VPL == 4) {
                    uint2 u0 = *(const uint2*)(hp + (size_t)s0 * K + lane * 4);
                    uint2 u1 = *(const uint2*)(hp + (size_t)s1 * K + lane * 4);
                    uint2 u2 = *(const uint2*)(hp + (size_t)s2 * K + lane * 4);
                    uint2 u3 = *(const uint2*)(hp + (size_t)s3 * K + lane * 4);
                    float2 a0 = __half22float2(*reinterpret_cast<__half2*>(&u0.x));
                    float2 b0 = __half22float2(*reinterpret_cast<__half2*>(&u0.y));
                    float2 a1 = __half22float2(*reinterpret_cast<__half2*>(&u1.x));
                    float2 b1 = __half22float2(*reinterpret_cast<__half2*>(&u1.y));
                    float2 a2 = __half22float2(*reinterpret_cast<__half2*>(&u2.x));
                    float2 b2 = __half22float2(*reinterpret_cast<__half2*>(&u2.y));
                    float2 a3 = __half22float2(*reinterpret_cast<__half2*>(&u3.x));
                    float2 b3 = __half22float2(*reinterpret_cast<__half2*>(&u3.y));
                    acc[0] += a0.x * w0 + a1.x * w1 + a2.x * w2 + a3.x * w3;
                    acc[1] += a0.y * w0 + a1.y * w1 + a2.y * w2 + a3.y * w3;
                    acc[2] += b0.x * w0 + b1.x * w1 + b2.x * w2 + b3.x * w3;
                    acc[3] += b0.y * w0 + b1.y * w1 + b2.y * w2 + b3.y * w3;
                } else {
                    unsigned u0 = *(const unsigned*)(hp + (size_t)s0 * K + lane * 2);
                    unsigned u1 = *(const unsigned*)(hp + (size_t)s1 * K + lane * 2);
                    unsigned u2 = *(const unsigned*)(hp + (size_t)s2 * K + lane * 2);
                    unsigned u3 = *(const unsigned*)(hp + (size_t)s3 * K + lane * 2);
                    float2 a0 = __half22float2(*reinterpret_cast<__half2*>(&u0));
                    float2 a1 = __half22float2(*reinterpret_cast<__half2*>(&u1));
                    float2 a2 = __half22float2(*reinterpret_cast<__half2*>(&u2));
                    float2 a3 = __half22float2(*reinterpret_cast<__half2*>(&u3));
                    acc[0] += a0.x * w0 + a1.x * w1 + a2.x * w2 + a3.x * w3;
                    acc[1] += a0.y * w0 + a1.y * w1 + a2.y * w2 + a3.y * w3;
                }
            }
            for (; j < end; j++) {
                int s = g_esrc[j];
                float w = g_enorm[j];
                if (VPL == 4) {
                    uint2 u = *(const uint2*)(hp + (size_t)s * K + lane * 4);
                    float2 f0 = __half22float2(*reinterpret_cast<__half2*>(&u.x));
                    float2 f1 = __half22float2(*reinterpret_cast<__half2*>(&u.y));
                    acc[0] += f0.x * w; acc[1] += f0.y * w; acc[2] += f1.x * w; acc[3] += f1.y * w;
                } else {
                    unsigned u = *(const unsigned*)(hp + (size_t)s * K + lane * 2);
                    float2 f0 = __half22float2(*reinterpret_cast<__half2*>(&u));
                    acc[0] += f0.x * w; acc[1] += f0.y * w;
                }
            }
#pragma unroll
            for (int v = 0; v < VPL; v++) sh[lr][lane * VPL + v] = acc[v];
        }
    }
    __syncthreads();

    // Phase B: GEMM from smem
    int tc = tid & 63, ty = tid >> 6;  // ty 0..3, 4 rows each
    const ull* __restrict__ Wll = (const ull*)W;
    ull acc[4];
    {
        float2 bb = *(const float2*)&b[2 * tc];
        ull binit = pack2(bb.x, bb.y);
#pragma unroll
        for (int r = 0; r < 4; r++) acc[r] = binit;
    }
    int rbase = ty * 4;
#pragma unroll 4
    for (int k = 0; k < K; k += 2) {
        ull w0 = Wll[k * (C / 2) + tc];
        ull w1 = Wll[(k + 1) * (C / 2) + tc];
#pragma unroll
        for (int r = 0; r < 4; r++) {
            float2 s2 = *(const float2*)&sh[rbase + r][k];
            acc[r] = ffma2(pack2(s2.x, s2.x), w0, acc[r]);
            acc[r] = ffma2(pack2(s2.y, s2.y), w1, acc[r]);
        }
    }

    if (!POOL) {
#pragma unroll
        for (int r = 0; r < 4; r++) {
            int row = row0 + rbase + r;
            if (row < n) {
                float xv, yv; unpack2(acc[r], xv, yv);
                __half2 o = __floats2half2_rn(fmaxf(xv, 0.0f), fmaxf(yv, 0.0f));
                *(__half2*)&g_h1[(size_t)row * C + 2 * tc] = o;
            }
        }
    } else {
        // relu + mean-pool accumulation (batch sorted -> run detection)
        int curg = -1;
        float rx = 0.0f, ry = 0.0f;
#pragma unroll
        for (int r = 0; r < 4; r++) {
            int row = row0 + rbase + r;
            if (row >= n) break;
            float xv, yv; unpack2(acc[r], xv, yv);
            xv = fmaxf(xv, 0.0f); yv = fmaxf(yv, 0.0f);
            int g = __ldg(&batch[row]);
            if (g != curg) {
                if (curg >= 0) {
                    atomicAdd(&g_psum[curg * 128 + 2 * tc], rx);
                    atomicAdd(&g_psum[curg * 128 + 2 * tc + 1], ry);
                }
                curg = g; rx = 0.0f; ry = 0.0f;
            }
            rx += xv; ry += yv;
        }
        if (curg >= 0) {
            atomicAdd(&g_psum[curg * 128 + 2 * tc], rx);
            atomicAdd(&g_psum[curg * 128 + 2 * tc + 1], ry);
        }
    }
}

// ---------------- MLP head ----------------
__global__ void k_fc(const float* __restrict__ Wf1, const float* __restrict__ bf1,
                     const float* __restrict__ Wf2, const float* __restrict__ bf2,
                     float* __restrict__ out) {
    int g = blockIdx.x;
    int t = threadIdx.x;  // 128
    __shared__ float p[128];
    __shared__ float f1[64];
    float inv = 1.0f / fmaxf(g_pcnt[g], 1.0f);
    p[t] = g_psum[g * 128 + t] * inv;
    __syncthreads();
    if (t < 64) {
        float acc = bf1[t];
#pragma unroll
        for (int k = 0; k < 128; k++) acc += p[k] * Wf1[k * 64 + t];
        f1[t] = fmaxf(acc, 0.0f);
    }
    __syncthreads();
    if (t < 10) {
        float acc = bf2[t];
#pragma unroll
        for (int k = 0; k < 64; k++) acc += f1[k] * Wf2[k * 10 + t];
        out[g * 10 + t] = acc;
    }
}

extern "C" void kernel_launch(void* const* d_in, const int* in_sizes, int n_in,
                              void* d_out, int out_size) {
    const float* x   = (const float*)d_in[0];
    const int* ei    = (const int*)d_in[1];
    const int* batch = (const int*)d_in[2];
    const float* W1  = (const float*)d_in[3];
    const float* b1  = (const float*)d_in[4];
    const float* W2  = (const float*)d_in[5];
    const float* b2  = (const float*)d_in[6];
    const float* W3  = (const float*)d_in[7];
    const float* b3  = (const float*)d_in[8];
    const float* Wf1 = (const float*)d_in[9];
    const float* bf1 = (const float*)d_in[10];
    const float* Wf2 = (const float*)d_in[11];
    const float* bf2 = (const float*)d_in[12];
    float* out = (float*)d_out;

    int N = in_sizes[0] / 3;
    int E = in_sizes[1] / 2;
    const int* src = ei;
    const int* dst = ei + E;
    int NB = (N + SCAN_B - 1) / SCAN_B;

    // CSR + norms (once per launch, reused by all 3 layers)
    k_zero<<<(N + 255) / 256, 256>>>(N);
    k_count<<<(E + 255) / 256, 256>>>(dst, batch, E, N);
    k_scanA<<<NB, SCAN_B>>>(N);
    k_scanC<<<(N + 255) / 256, 256>>>(N, E, NB);
    k_fill<<<(E + 255) / 256, 256>>>(src, dst, E);

    // Fused layers
    k_layer1<<<(N + 63) / 64, 256>>>(x, W1, b1, N);
    k_layer<64, 2, false><<<(N + 15) / 16, 256>>>(W2, b2, batch, N);
    k_layer<128, 4, true><<<(N + 15) / 16, 256>>>(W3, b3, batch, N);

    // Head
    k_fc<<<GRAPHS, 128>>>(Wf1, bf1, Wf2, bf2, out);
}